// round 1
// baseline (speedup 1.0000x reference)
#include <cuda_runtime.h>
#include <math.h>

#define NN 50000
#define EE 500000
#define DEPTH 4

// ---- scratch (no allocation allowed; device globals) ----
__device__ float g_P[(size_t)NN * 128];     // per-node projections [Pa | Pb]
__device__ float g_t[(size_t)NN * 64];      // sum_e C*h2
__device__ float g_vagg[(size_t)NN * 9];
__device__ float g_C[EE];
__device__ float g_cnt[NN];
__device__ float g_Csum[NN];
__device__ float g_Wcomb[DEPTH * 64 * 64];  // W3s @ Wn1b per layer
__device__ float g_bcomb[DEPTH * 64];       // b3s @ Wn1b per layer

__device__ __forceinline__ float silu_f(float x) {
    return x * (1.0f / (1.0f + __expf(-x)));
}

// ---------------------------------------------------------------- utility
__global__ void zero_nc_kernel() {
    int i = blockIdx.x * 256 + threadIdx.x;
    if (i < NN) { g_cnt[i] = 0.0f; g_Csum[i] = 0.0f; }
}

__global__ void zero_layer_kernel() {
    int i = blockIdx.x * 256 + threadIdx.x;
    if (i < NN * 64) g_t[i] = 0.0f;
    if (i < NN * 9)  g_vagg[i] = 0.0f;
}

__global__ void copy_in_kernel(const float* __restrict__ s_in,
                               const float* __restrict__ v_in,
                               float* __restrict__ s_out,
                               float* __restrict__ v_out) {
    int i = blockIdx.x * 256 + threadIdx.x;
    if (i < NN * 128) s_out[i] = s_in[i];
    if (i < NN * 9)   v_out[i] = v_in[i];
}

__global__ void prep_edge_kernel(const int* __restrict__ eidx,
                                 const float* __restrict__ dd) {
    int e = blockIdx.x * 256 + threadIdx.x;
    if (e < EE) {
        float dv = dd[e];
        float C = (dv < 5.0f) ? 0.5f * (cospif(dv * 0.2f) + 1.0f) : 0.0f;
        g_C[e] = C;
        int dn = eidx[e];
        atomicAdd(&g_cnt[dn], 1.0f);
        atomicAdd(&g_Csum[dn], C);
    }
}

// Wcomb[l] = W3s[l] @ Wn1b[l]  (64x128 @ 128x64); bcomb = b3s @ Wn1b
__global__ __launch_bounds__(256) void prep_wcomb_kernel(
    const float* __restrict__ W3g, const float* __restrict__ b3g,
    const float* __restrict__ Wn1g)
{
    extern __shared__ float sm[];
    float* A = sm;              // 64*128  (W3s, row-major k x m)
    float* B = A + 64 * 128;    // 128*64  (Wn1b, m x j)
    int l = blockIdx.x, tid = threadIdx.x;
    const float* W3l = W3g + l * (64 * 134);
    const float* Wb  = Wn1g + l * (256 * 64) + 128 * 64;
    for (int i = tid; i < 64 * 128; i += 256) {
        int m = i & 127, k = i >> 7;
        A[k * 128 + m] = W3l[k * 134 + m];
    }
    for (int i = tid; i < 128 * 64; i += 256) B[i] = Wb[i];
    __syncthreads();
    for (int i = tid; i < 64 * 64; i += 256) {
        int k = i >> 6, j = i & 63;
        float acc = 0.0f;
        #pragma unroll 8
        for (int m = 0; m < 128; m++)
            acc = fmaf(A[k * 128 + m], B[m * 64 + j], acc);
        g_Wcomb[l * 4096 + i] = acc;
    }
    if (tid < 64) {
        float acc = 0.0f;
        #pragma unroll 8
        for (int m = 0; m < 128; m++)
            acc = fmaf(b3g[l * 134 + m], B[m * 64 + tid], acc);
        g_bcomb[l * 64 + tid] = acc;
    }
}

// ------------------------------------------------- P = s @ [W1a | W1b]
__global__ __launch_bounds__(256) void node_pre_kernel(
    const float* __restrict__ s_cur, const float* __restrict__ W1g, int layer)
{
    extern __shared__ float sm[];
    float* sT = sm;             // [128][68]  k-major (feature x node)
    float* Ws = sT + 128 * 68;  // [128][128]
    const int tid = threadIdx.x;
    const int nb = blockIdx.x * 64;

    for (int i = tid; i < 64 * 128; i += 256) {
        int k = i & 127, nl = i >> 7;
        int n = nb + nl; if (n >= NN) n = NN - 1;
        sT[k * 68 + nl] = s_cur[(size_t)n * 128 + k];
    }
    const float* W1l = W1g + layer * (257 * 64);
    for (int i = tid; i < 128 * 128; i += 256) {
        int j = i & 127, k = i >> 7;
        Ws[i] = (j < 64) ? W1l[k * 64 + j] : W1l[(128 + k) * 64 + (j - 64)];
    }
    __syncthreads();

    const int n0 = (tid & 15) * 4;
    const int j0 = (tid >> 4) * 8;
    float acc[4][8];
    #pragma unroll
    for (int ii = 0; ii < 4; ii++)
        #pragma unroll
        for (int jj = 0; jj < 8; jj++) acc[ii][jj] = 0.0f;

    #pragma unroll 8
    for (int k = 0; k < 128; k++) {
        float4 a  = *(const float4*)(sT + k * 68 + n0);
        float4 b0 = *(const float4*)(Ws + k * 128 + j0);
        float4 b4 = *(const float4*)(Ws + k * 128 + j0 + 4);
        float av[4] = {a.x, a.y, a.z, a.w};
        float bv[8] = {b0.x, b0.y, b0.z, b0.w, b4.x, b4.y, b4.z, b4.w};
        #pragma unroll
        for (int ii = 0; ii < 4; ii++)
            #pragma unroll
            for (int jj = 0; jj < 8; jj++)
                acc[ii][jj] = fmaf(av[ii], bv[jj], acc[ii][jj]);
    }
    #pragma unroll
    for (int ii = 0; ii < 4; ii++) {
        int n = nb + n0 + ii;
        if (n < NN) {
            float4 o0 = {acc[ii][0], acc[ii][1], acc[ii][2], acc[ii][3]};
            float4 o4 = {acc[ii][4], acc[ii][5], acc[ii][6], acc[ii][7]};
            *(float4*)(g_P + (size_t)n * 128 + j0)     = o0;
            *(float4*)(g_P + (size_t)n * 128 + j0 + 4) = o4;
        }
    }
}

// ------------------------------------------------- edge kernel (128 edges/CTA)
__global__ __launch_bounds__(256) void edge_kernel(
    const int* __restrict__ eidx, const float* __restrict__ dd,
    const float* __restrict__ rr,
    const float* __restrict__ W1g, const float* __restrict__ b1g,
    const float* __restrict__ W2g, const float* __restrict__ b2g,
    const float* __restrict__ W3g, const float* __restrict__ b3g,
    const float* __restrict__ v_cur, int layer)
{
    extern __shared__ float sm[];
    float* W2s  = sm;                    // [64][68]
    float* h1T  = W2s + 64 * 68;         // [64][132]  (k-major: h1T[k][e])
    float* h2s  = h1T + 64 * 132;        // [128][68]
    float* W3vs = h2s + 128 * 68;        // [64][6]
    float* gvr  = W3vs + 384;            // [128][8] (gv:0..2, gr:3..5)
    float* w1ds = gvr + 1024;            // 64
    float* b1s  = w1ds + 64;             // 64
    float* b2s  = b1s + 64;              // 64
    float* b3vs = b2s + 64;              // 8
    float* Cs   = b3vs + 8;              // 128
    float* dAs  = Cs + 128;              // 128
    int*   dstA = (int*)(dAs + 128);     // 128
    int*   srcA = dstA + 128;            // 128

    const int tid = threadIdx.x;
    const int eb = blockIdx.x * 128;

    if (tid < 128) {
        int e = eb + tid;
        bool valid = (e < EE);
        int ec = valid ? e : 0;
        dstA[tid] = eidx[ec];
        srcA[tid] = eidx[EE + ec];
        Cs[tid]  = valid ? g_C[ec] : 0.0f;
        dAs[tid] = valid ? dd[ec] : 0.0f;
    }
    const float* W2l = W2g + layer * (64 * 64);
    for (int i = tid; i < 64 * 64; i += 256)
        W2s[(i >> 6) * 68 + (i & 63)] = W2l[i];
    const float* W3l = W3g + layer * (64 * 134);
    for (int i = tid; i < 64 * 6; i += 256) {
        int k = i / 6, j = i - k * 6;
        W3vs[i] = W3l[k * 134 + 128 + j];
    }
    if (tid < 64) {
        w1ds[tid] = W1g[layer * (257 * 64) + 256 * 64 + tid];
        b1s[tid]  = b1g[layer * 64 + tid];
        b2s[tid]  = b2g[layer * 64 + tid];
    }
    if (tid < 6) b3vs[tid] = b3g[layer * 134 + 128 + tid];
    __syncthreads();

    // Phase A: h1 = silu(Pa[dst] + Pb[src] + d*w1d + b1), stored k-major
    #pragma unroll 8
    for (int i = 0; i < 32; i++) {
        int idx = i * 256 + tid;
        int c = idx & 63, e = idx >> 6;
        float pre = g_P[(size_t)dstA[e] * 128 + c]
                  + g_P[(size_t)srcA[e] * 128 + 64 + c]
                  + dAs[e] * w1ds[c] + b1s[c];
        h1T[c * 132 + e] = silu_f(pre);
    }
    __syncthreads();

    // Phase B: h2 = silu(h1 @ W2 + b2)   (128x64x64 GEMM, 4x8 microtile)
    {
        const int e0 = (tid >> 3) * 4;
        const int c0 = (tid & 7) * 8;
        float acc[4][8];
        #pragma unroll
        for (int ii = 0; ii < 4; ii++)
            #pragma unroll
            for (int jj = 0; jj < 8; jj++) acc[ii][jj] = 0.0f;
        #pragma unroll 8
        for (int k = 0; k < 64; k++) {
            float4 a  = *(const float4*)(h1T + k * 132 + e0);
            float4 b0 = *(const float4*)(W2s + k * 68 + c0);
            float4 b4 = *(const float4*)(W2s + k * 68 + c0 + 4);
            float av[4] = {a.x, a.y, a.z, a.w};
            float bv[8] = {b0.x, b0.y, b0.z, b0.w, b4.x, b4.y, b4.z, b4.w};
            #pragma unroll
            for (int ii = 0; ii < 4; ii++)
                #pragma unroll
                for (int jj = 0; jj < 8; jj++)
                    acc[ii][jj] = fmaf(av[ii], bv[jj], acc[ii][jj]);
        }
        #pragma unroll
        for (int ii = 0; ii < 4; ii++) {
            float4 o0, o4;
            o0.x = silu_f(acc[ii][0] + b2s[c0 + 0]);
            o0.y = silu_f(acc[ii][1] + b2s[c0 + 1]);
            o0.z = silu_f(acc[ii][2] + b2s[c0 + 2]);
            o0.w = silu_f(acc[ii][3] + b2s[c0 + 3]);
            o4.x = silu_f(acc[ii][4] + b2s[c0 + 4]);
            o4.y = silu_f(acc[ii][5] + b2s[c0 + 5]);
            o4.z = silu_f(acc[ii][6] + b2s[c0 + 6]);
            o4.w = silu_f(acc[ii][7] + b2s[c0 + 7]);
            *(float4*)(h2s + (e0 + ii) * 68 + c0)     = o0;
            *(float4*)(h2s + (e0 + ii) * 68 + c0 + 4) = o4;
        }
    }
    __syncthreads();

    // Phase C: gv/gr = h2 @ W3v + b3v (6 outputs/edge)
    for (int idx = tid; idx < 128 * 6; idx += 256) {
        int e = idx / 6, j = idx - e * 6;
        float a2 = b3vs[j];
        #pragma unroll 8
        for (int k = 0; k < 64; k++)
            a2 = fmaf(h2s[e * 68 + k], W3vs[k * 6 + j], a2);
        gvr[e * 8 + j] = a2;
    }
    __syncthreads();

    // Phase D: t[dst] += C * h2   (coalesced 64-float rows per edge)
    #pragma unroll 4
    for (int i = 0; i < 32; i++) {
        int idx = i * 256 + tid;
        int c = idx & 63, e = idx >> 6;
        atomicAdd(&g_t[(size_t)dstA[e] * 64 + c], Cs[e] * h2s[e * 68 + c]);
    }

    // Phase E: v_agg[dst] += (v[src]*gv + r*gr)*C
    for (int idx = tid; idx < 128 * 9; idx += 256) {
        int e = idx / 9, p = idx - e * 9;
        int iv = p / 3, x = p - iv * 3;
        int eg = eb + e; if (eg >= EE) eg = EE - 1;
        float val = (v_cur[(size_t)srcA[e] * 9 + p] * gvr[e * 8 + iv]
                   + rr[(size_t)eg * 3 + x]        * gvr[e * 8 + 3 + iv]) * Cs[e];
        atomicAdd(&g_vagg[(size_t)dstA[e] * 9 + p], val);
    }
}

// ------------------------------------------------- node update
// u = silu(s@Wn1a + t@Wcomb + Csum*bcomb + bn1);  s += u@Wn2 + bn2;  v += vagg/cnt
__global__ __launch_bounds__(256) void node_post_kernel(
    float* __restrict__ s_cur, float* __restrict__ v_cur,
    const float* __restrict__ Wn1g, const float* __restrict__ bn1g,
    const float* __restrict__ Wn2g, const float* __restrict__ bn2g,
    int layer)
{
    extern __shared__ float sm[];
    float* sT   = sm;              // [128][68]
    float* tT   = sT + 128 * 68;   // [64][68]   (reused as uT)
    float* Wa   = tT + 64 * 68;    // 128*64     (reused as Wn2 64*128)
    float* Wc   = Wa + 8192;       // 64*64
    float* bn1s = Wc + 4096;       // 64
    float* bcs  = bn1s + 64;       // 64
    float* bn2s = bcs + 64;        // 128
    float* csum = bn2s + 128;      // 64
    const int tid = threadIdx.x;
    const int nb = blockIdx.x * 64;

    for (int i = tid; i < 64 * 128; i += 256) {
        int k = i & 127, nl = i >> 7;
        int n = nb + nl; if (n >= NN) n = NN - 1;
        sT[k * 68 + nl] = s_cur[(size_t)n * 128 + k];
    }
    for (int i = tid; i < 64 * 64; i += 256) {
        int k = i & 63, nl = i >> 6;
        int n = nb + nl; if (n >= NN) n = NN - 1;
        tT[k * 68 + nl] = g_t[(size_t)n * 64 + k];
    }
    const float* Wn1l = Wn1g + layer * (256 * 64);
    for (int i = tid; i < 128 * 64; i += 256) Wa[i] = Wn1l[i];
    for (int i = tid; i < 64 * 64; i += 256)  Wc[i] = g_Wcomb[layer * 4096 + i];
    if (tid < 64) {
        bn1s[tid] = bn1g[layer * 64 + tid];
        bcs[tid]  = g_bcomb[layer * 64 + tid];
        int n = nb + tid; if (n >= NN) n = NN - 1;
        csum[tid] = g_Csum[n];
    }
    if (tid < 128) bn2s[tid] = bn2g[layer * 128 + tid];
    __syncthreads();

    const int n0 = (tid & 15) * 4;
    const int j0 = (tid >> 4) * 4;
    float acc1[4][4];
    #pragma unroll
    for (int ii = 0; ii < 4; ii++)
        #pragma unroll
        for (int jj = 0; jj < 4; jj++) acc1[ii][jj] = 0.0f;

    #pragma unroll 8
    for (int k = 0; k < 128; k++) {
        float4 a = *(const float4*)(sT + k * 68 + n0);
        float4 b = *(const float4*)(Wa + k * 64 + j0);
        float av[4] = {a.x, a.y, a.z, a.w};
        float bv[4] = {b.x, b.y, b.z, b.w};
        #pragma unroll
        for (int ii = 0; ii < 4; ii++)
            #pragma unroll
            for (int jj = 0; jj < 4; jj++)
                acc1[ii][jj] = fmaf(av[ii], bv[jj], acc1[ii][jj]);
    }
    #pragma unroll 8
    for (int k = 0; k < 64; k++) {
        float4 a = *(const float4*)(tT + k * 68 + n0);
        float4 b = *(const float4*)(Wc + k * 64 + j0);
        float av[4] = {a.x, a.y, a.z, a.w};
        float bv[4] = {b.x, b.y, b.z, b.w};
        #pragma unroll
        for (int ii = 0; ii < 4; ii++)
            #pragma unroll
            for (int jj = 0; jj < 4; jj++)
                acc1[ii][jj] = fmaf(av[ii], bv[jj], acc1[ii][jj]);
    }
    float u[4][4];
    #pragma unroll
    for (int ii = 0; ii < 4; ii++)
        #pragma unroll
        for (int jj = 0; jj < 4; jj++)
            u[ii][jj] = silu_f(acc1[ii][jj] + csum[n0 + ii] * bcs[j0 + jj] + bn1s[j0 + jj]);
    __syncthreads();   // tT/Wa reads done; safe to repurpose

    float* uT = tT;
    #pragma unroll
    for (int ii = 0; ii < 4; ii++)
        #pragma unroll
        for (int jj = 0; jj < 4; jj++)
            uT[(j0 + jj) * 68 + (n0 + ii)] = u[ii][jj];
    float* W2n = Wa;
    const float* Wn2l = Wn2g + layer * (64 * 128);
    for (int i = tid; i < 64 * 128; i += 256) W2n[i] = Wn2l[i];
    __syncthreads();

    const int i0 = (tid >> 4) * 8;
    float acc2[4][8];
    #pragma unroll
    for (int ii = 0; ii < 4; ii++)
        #pragma unroll
        for (int jj = 0; jj < 8; jj++) acc2[ii][jj] = 0.0f;
    #pragma unroll 8
    for (int k = 0; k < 64; k++) {
        float4 a  = *(const float4*)(uT + k * 68 + n0);
        float4 b0 = *(const float4*)(W2n + k * 128 + i0);
        float4 b4 = *(const float4*)(W2n + k * 128 + i0 + 4);
        float av[4] = {a.x, a.y, a.z, a.w};
        float bv[8] = {b0.x, b0.y, b0.z, b0.w, b4.x, b4.y, b4.z, b4.w};
        #pragma unroll
        for (int ii = 0; ii < 4; ii++)
            #pragma unroll
            for (int jj = 0; jj < 8; jj++)
                acc2[ii][jj] = fmaf(av[ii], bv[jj], acc2[ii][jj]);
    }
    #pragma unroll
    for (int ii = 0; ii < 4; ii++) {
        int n = nb + n0 + ii;
        if (n < NN) {
            float4 o0, o4;
            o0.x = sT[(i0 + 0) * 68 + n0 + ii] + acc2[ii][0] + bn2s[i0 + 0];
            o0.y = sT[(i0 + 1) * 68 + n0 + ii] + acc2[ii][1] + bn2s[i0 + 1];
            o0.z = sT[(i0 + 2) * 68 + n0 + ii] + acc2[ii][2] + bn2s[i0 + 2];
            o0.w = sT[(i0 + 3) * 68 + n0 + ii] + acc2[ii][3] + bn2s[i0 + 3];
            o4.x = sT[(i0 + 4) * 68 + n0 + ii] + acc2[ii][4] + bn2s[i0 + 4];
            o4.y = sT[(i0 + 5) * 68 + n0 + ii] + acc2[ii][5] + bn2s[i0 + 5];
            o4.z = sT[(i0 + 6) * 68 + n0 + ii] + acc2[ii][6] + bn2s[i0 + 6];
            o4.w = sT[(i0 + 7) * 68 + n0 + ii] + acc2[ii][7] + bn2s[i0 + 7];
            *(float4*)(s_cur + (size_t)n * 128 + i0)     = o0;
            *(float4*)(s_cur + (size_t)n * 128 + i0 + 4) = o4;
        }
    }
    for (int idx = tid; idx < 64 * 9; idx += 256) {
        int nl = idx / 9, p = idx - nl * 9;
        int n = nb + nl;
        if (n < NN) {
            float ic = 1.0f / fmaxf(g_cnt[n], 1.0f);
            v_cur[(size_t)n * 9 + p] += g_vagg[(size_t)n * 9 + p] * ic;
        }
    }
}

// ---------------------------------------------------------------- launch
extern "C" void kernel_launch(void* const* d_in, const int* in_sizes, int n_in,
                              void* d_out, int out_size)
{
    const float* s_in  = (const float*)d_in[0];
    const float* v_in  = (const float*)d_in[1];
    const int*   eidx  = (const int*)d_in[2];
    const float* dd    = (const float*)d_in[3];
    const float* rr    = (const float*)d_in[4];
    const float* W1g   = (const float*)d_in[5];
    const float* b1g   = (const float*)d_in[6];
    const float* W2g   = (const float*)d_in[7];
    const float* b2g   = (const float*)d_in[8];
    const float* W3g   = (const float*)d_in[9];
    const float* b3g   = (const float*)d_in[10];
    const float* Wn1g  = (const float*)d_in[11];
    const float* bn1g  = (const float*)d_in[12];
    const float* Wn2g  = (const float*)d_in[13];
    const float* bn2g  = (const float*)d_in[14];

    float* s_cur = (float*)d_out;                 // output s region is the working buffer
    float* v_cur = s_cur + (size_t)NN * 128;      // output v region

    const int EDGE_SMEM  = (64*68 + 64*132 + 128*68 + 384 + 1024 + 64*3 + 8 + 128*2 + 128*2) * 4;
    const int PRE_SMEM   = (128*68 + 128*128) * 4;
    const int POST_SMEM  = (128*68 + 64*68 + 8192 + 4096 + 64 + 64 + 128 + 64) * 4;
    const int WCOMB_SMEM = (64*128 + 128*64) * 4;

    cudaFuncSetAttribute(edge_kernel,      cudaFuncAttributeMaxDynamicSharedMemorySize, EDGE_SMEM);
    cudaFuncSetAttribute(node_pre_kernel,  cudaFuncAttributeMaxDynamicSharedMemorySize, PRE_SMEM);
    cudaFuncSetAttribute(node_post_kernel, cudaFuncAttributeMaxDynamicSharedMemorySize, POST_SMEM);
    cudaFuncSetAttribute(prep_wcomb_kernel,cudaFuncAttributeMaxDynamicSharedMemorySize, WCOMB_SMEM);

    zero_nc_kernel<<<(NN + 255) / 256, 256>>>();
    copy_in_kernel<<<(NN * 128 + 255) / 256, 256>>>(s_in, v_in, s_cur, v_cur);
    prep_edge_kernel<<<(EE + 255) / 256, 256>>>(eidx, dd);
    prep_wcomb_kernel<<<DEPTH, 256, WCOMB_SMEM>>>(W3g, b3g, Wn1g);

    const int NBLK = (NN + 63) / 64;
    const int EBLK = (EE + 127) / 128;
    for (int l = 0; l < DEPTH; l++) {
        zero_layer_kernel<<<(NN * 64 + 255) / 256, 256>>>();
        node_pre_kernel<<<NBLK, 256, PRE_SMEM>>>(s_cur, W1g, l);
        edge_kernel<<<EBLK, 256, EDGE_SMEM>>>(eidx, dd, rr, W1g, b1g, W2g, b2g,
                                              W3g, b3g, v_cur, l);
        node_post_kernel<<<NBLK, 256, POST_SMEM>>>(s_cur, v_cur, Wn1g, bn1g,
                                                   Wn2g, bn2g, l);
    }
    (void)in_sizes; (void)n_in; (void)out_size;
}